// round 8
// baseline (speedup 1.0000x reference)
#include <cuda_runtime.h>
#include <cuda_bf16.h>
#include <cstdint>

#define TT 16          // time steps
#define BB 16          // batch
#define CC 256         // channels C (and Cc)
#define DD 512         // 2*C
#define HW 1024        // H*W

// Scratch (no allocation allowed)
__device__ float g_params[TT * BB * DD];   // [T,B,2C]

// ---------------------------------------------------------------------------
// Fused LIF+GEMM head. Grid: 256 blocks (16 b x 16 d-chunks) x 256 threads.
// Publishes g_params, fences, then triggers programmatic launch completion
// so the dependent film grid can start before this grid fully retires.
// ---------------------------------------------------------------------------
__global__ void __launch_bounds__(256) head_kernel(
    const float* __restrict__ cond,
    const float* __restrict__ Wm,
    const float* __restrict__ bias) {
    __shared__ float s_sp[TT][CC + 4];     // +4 pad
    int tid   = threadIdx.x;
    int b     = blockIdx.x >> 4;
    int dbase = (blockIdx.x & 15) << 5;    // 32 d's per block

    // --- LIF scan (16 hoisted cond loads -> register recurrence) ---
    {
        int cc = tid;
        float xv[TT];
#pragma unroll
        for (int t = 0; t < TT; ++t)
            xv[t] = cond[(t * BB + b) * CC + cc];
        float v = 0.0f;
#pragma unroll
        for (int t = 0; t < TT; ++t) {
            v = v + (xv[t] - v) * 0.5f;              // charge (TAU=2)
            float s = (v >= 1.0f) ? 1.0f : 0.0f;     // fire
            s_sp[t][cc] = s;
            v = (1.0f - s) * v;                      // hard reset
        }
    }
    __syncthreads();

    // --- GEMM: thread = (d-lane 0..31, t-pair 0..7); W in native layout ---
    int dl = tid >> 3;
    int tp = tid & 7;
    int d  = dbase + dl;
    int t0 = tp * 2, t1 = t0 + 1;

    const float4* __restrict__ w4 = (const float4*)(Wm + (size_t)d * CC);
    const float4* __restrict__ s0 = (const float4*)&s_sp[t0][0];
    const float4* __restrict__ s1 = (const float4*)&s_sp[t1][0];

    float a0 = bias[d], a1 = a0;
#pragma unroll 8
    for (int k = 0; k < CC / 4; ++k) {
        float4 w = w4[k];
        float4 p = s0[k];
        float4 q = s1[k];
        a0 = fmaf(p.x, w.x, a0); a0 = fmaf(p.y, w.y, a0);
        a0 = fmaf(p.z, w.z, a0); a0 = fmaf(p.w, w.w, a0);
        a1 = fmaf(q.x, w.x, a1); a1 = fmaf(q.y, w.y, a1);
        a1 = fmaf(q.z, w.z, a1); a1 = fmaf(q.w, w.w, a1);
    }
    g_params[(t0 * BB + b) * DD + d] = a0;
    g_params[(t1 * BB + b) * DD + d] = a1;

    __threadfence();                        // publish params
#if __CUDA_ARCH__ >= 900
    cudaTriggerProgrammaticLaunchCompletion();
#endif
}

// ---------------------------------------------------------------------------
// FiLM elementwise (measured 77.4us / 6.27TB/s body). Launched with PDL:
// the 8 x-loads (independent of the head) are issued BEFORE
// cudaGridDependencySynchronize(); only the g_params reads wait.
// out = (1+gamma)*x + beta
// ---------------------------------------------------------------------------
__global__ void __launch_bounds__(256) film_kernel(
    const float4* __restrict__ x, float4* __restrict__ out) {
    unsigned row0 = blockIdx.x * 8;
    unsigned tb   = row0 >> 8;
    unsigned c0   = row0 & (CC - 1);

    size_t base = (size_t)row0 * 256 + threadIdx.x;

    float4 v0 = x[base];
    float4 v1 = x[base + 256];
    float4 v2 = x[base + 512];
    float4 v3 = x[base + 768];
    float4 v4 = x[base + 1024];
    float4 v5 = x[base + 1280];
    float4 v6 = x[base + 1536];
    float4 v7 = x[base + 1792];

#if __CUDA_ARCH__ >= 900
    cudaGridDependencySynchronize();        // wait for head's trigger
#endif

    const float4* __restrict__ p4 = (const float4*)(g_params + tb * DD + c0);
    float4 ga = p4[0];
    float4 gb = p4[1];
    float4 ba = p4[CC / 4];
    float4 bb = p4[CC / 4 + 1];

    float g0 = 1.0f + ga.x, g1 = 1.0f + ga.y, g2 = 1.0f + ga.z, g3 = 1.0f + ga.w;
    float g4 = 1.0f + gb.x, g5 = 1.0f + gb.y, g6 = 1.0f + gb.z, g7 = 1.0f + gb.w;

    float4 o;
    o.x = fmaf(g0, v0.x, ba.x); o.y = fmaf(g0, v0.y, ba.x);
    o.z = fmaf(g0, v0.z, ba.x); o.w = fmaf(g0, v0.w, ba.x);
    out[base] = o;
    o.x = fmaf(g1, v1.x, ba.y); o.y = fmaf(g1, v1.y, ba.y);
    o.z = fmaf(g1, v1.z, ba.y); o.w = fmaf(g1, v1.w, ba.y);
    out[base + 256] = o;
    o.x = fmaf(g2, v2.x, ba.z); o.y = fmaf(g2, v2.y, ba.z);
    o.z = fmaf(g2, v2.z, ba.z); o.w = fmaf(g2, v2.w, ba.z);
    out[base + 512] = o;
    o.x = fmaf(g3, v3.x, ba.w); o.y = fmaf(g3, v3.y, ba.w);
    o.z = fmaf(g3, v3.z, ba.w); o.w = fmaf(g3, v3.w, ba.w);
    out[base + 768] = o;
    o.x = fmaf(g4, v4.x, bb.x); o.y = fmaf(g4, v4.y, bb.x);
    o.z = fmaf(g4, v4.z, bb.x); o.w = fmaf(g4, v4.w, bb.x);
    out[base + 1024] = o;
    o.x = fmaf(g5, v5.x, bb.y); o.y = fmaf(g5, v5.y, bb.y);
    o.z = fmaf(g5, v5.z, bb.y); o.w = fmaf(g5, v5.w, bb.y);
    out[base + 1280] = o;
    o.x = fmaf(g6, v6.x, bb.z); o.y = fmaf(g6, v6.y, bb.z);
    o.z = fmaf(g6, v6.z, bb.z); o.w = fmaf(g6, v6.w, bb.z);
    out[base + 1536] = o;
    o.x = fmaf(g7, v7.x, bb.w); o.y = fmaf(g7, v7.y, bb.w);
    o.z = fmaf(g7, v7.z, bb.w); o.w = fmaf(g7, v7.w, bb.w);
    out[base + 1792] = o;
}

// ---------------------------------------------------------------------------
extern "C" void kernel_launch(void* const* d_in, const int* in_sizes, int n_in,
                              void* d_out, int out_size) {
    const float* x    = (const float*)d_in[0];   // [T,B,C,H,W]
    const float* cond = (const float*)d_in[1];   // [T,B,Cc]
    const float* Wm   = (const float*)d_in[2];   // [2C,Cc]
    const float* bias = (const float*)d_in[3];   // [2C]
    float* out = (float*)d_out;

    head_kernel<<<BB * 16, 256>>>(cond, Wm, bias);

    // Dependent launch: film may begin as soon as head triggers completion.
    cudaLaunchConfig_t cfg = {};
    cfg.gridDim  = dim3(TT * BB * CC / 8);
    cfg.blockDim = dim3(256);
    cfg.dynamicSmemBytes = 0;
    cfg.stream = 0;   // legacy default stream (captured by harness)
    cudaLaunchAttribute attr[1];
    attr[0].id = cudaLaunchAttributeProgrammaticStreamSerialization;
    attr[0].val.programmaticStreamSerializationAllowed = 1;
    cfg.attrs = attr;
    cfg.numAttrs = 1;
    cudaLaunchKernelEx(&cfg, film_kernel, (const float4*)x, (float4*)out);
}

// round 10
// speedup vs baseline: 1.1514x; 1.1514x over previous
#include <cuda_runtime.h>
#include <cuda_bf16.h>
#include <cstdint>

#define TT 16          // time steps
#define BB 16          // batch
#define CC 256         // channels C (and Cc)
#define DD 512         // 2*C
#define HW 1024        // H*W

// ---------------------------------------------------------------------------
// Single fused kernel, one launch. Grid = 8192 blocks x 256 threads; block
// `bid` owns 8 consecutive channels of one (t,b) slice -- identical tiling
// to the measured 77.4us film kernel.
//
// Phase A: LIF scan, block-local. Thread cc loads cond[(t',b,cc)] for all 16
//          t' (independent -> MLP=16, L2-resident after first wave), runs the
//          recurrence in registers, keeps the spike at THIS block's t.
// Phase B: the 16 params this block needs (gamma/beta for channels c0..c0+7)
//          = 16 dot products of length 256. 16 threads per output, k=16i+ch
//          (spikes conflict-free in smem, W coalesced), 4-stage shfl reduce.
// Phase C: the proven MLP=8 FiLM body, params broadcast from smem.
// No global scratch, no inter-block sync, no second launch.
// ---------------------------------------------------------------------------
__global__ void __launch_bounds__(256) fused_kernel(
    const float4* __restrict__ x,
    const float*  __restrict__ cond,
    const float*  __restrict__ Wm,
    const float*  __restrict__ bias,
    float4*       __restrict__ out) {
    __shared__ float s_sp[CC];      // spikes at this block's t
    __shared__ float s_par[16];     // 8 gamma | 8 beta

    int tid  = threadIdx.x;
    unsigned row0 = blockIdx.x * 8;         // first channel-row
    unsigned tb   = row0 >> 8;              // t*BB + b
    unsigned c0   = row0 & (CC - 1);
    int t = (int)(tb >> 4);                 // this block's time step
    int b = (int)(tb & 15);

    // --- Phase A: LIF scan for (b, cc=tid); keep spike at step t ---
    {
        int cc = tid;
        float xv[TT];
#pragma unroll
        for (int tp = 0; tp < TT; ++tp)     // independent loads, MLP=16
            xv[tp] = cond[(tp * BB + b) * CC + cc];
        float v = 0.0f, s_t = 0.0f;
#pragma unroll
        for (int tp = 0; tp < TT; ++tp) {
            v = v + (xv[tp] - v) * 0.5f;             // charge (TAU=2)
            float s = (v >= 1.0f) ? 1.0f : 0.0f;     // fire
            if (tp == t) s_t = s;                    // predicated select
            v = (1.0f - s) * v;                      // hard reset
        }
        s_sp[cc] = s_t;
    }
    __syncthreads();

    // --- Phase B: 16 dot products (8 gamma rows, 8 beta rows) ---
    {
        int o  = tid >> 4;                  // output 0..15
        int ch = tid & 15;                  // k-chunk lane 0..15
        int d  = (o < 8) ? (int)(c0 + o) : (int)(CC + c0 + (o - 8));
        const float* __restrict__ wr = Wm + (size_t)d * CC;

        float a = 0.0f;
#pragma unroll
        for (int i = 0; i < 16; ++i) {
            int k = i * 16 + ch;            // conflict-free smem, coalesced W
            a = fmaf(s_sp[k], wr[k], a);
        }
#pragma unroll
        for (int m = 8; m >= 1; m >>= 1)    // reduce within 16-lane group
            a += __shfl_xor_sync(0xFFFFFFFFu, a, m);
        if (ch == 0) s_par[o] = a + bias[d];
    }
    __syncthreads();

    // --- Phase C: FiLM body (measured-77us shape: 8 hoisted float4 loads) ---
    size_t base = (size_t)row0 * 256 + tid;

    float4 v0 = x[base];
    float4 v1 = x[base + 256];
    float4 v2 = x[base + 512];
    float4 v3 = x[base + 768];
    float4 v4 = x[base + 1024];
    float4 v5 = x[base + 1280];
    float4 v6 = x[base + 1536];
    float4 v7 = x[base + 1792];

    float g0 = 1.0f + s_par[0], g1 = 1.0f + s_par[1];
    float g2 = 1.0f + s_par[2], g3 = 1.0f + s_par[3];
    float g4 = 1.0f + s_par[4], g5 = 1.0f + s_par[5];
    float g6 = 1.0f + s_par[6], g7 = 1.0f + s_par[7];
    float b0 = s_par[8],  b1 = s_par[9],  b2 = s_par[10], b3 = s_par[11];
    float b4 = s_par[12], b5 = s_par[13], b6 = s_par[14], b7 = s_par[15];

    float4 o;
    o.x = fmaf(g0, v0.x, b0); o.y = fmaf(g0, v0.y, b0);
    o.z = fmaf(g0, v0.z, b0); o.w = fmaf(g0, v0.w, b0);
    out[base] = o;
    o.x = fmaf(g1, v1.x, b1); o.y = fmaf(g1, v1.y, b1);
    o.z = fmaf(g1, v1.z, b1); o.w = fmaf(g1, v1.w, b1);
    out[base + 256] = o;
    o.x = fmaf(g2, v2.x, b2); o.y = fmaf(g2, v2.y, b2);
    o.z = fmaf(g2, v2.z, b2); o.w = fmaf(g2, v2.w, b2);
    out[base + 512] = o;
    o.x = fmaf(g3, v3.x, b3); o.y = fmaf(g3, v3.y, b3);
    o.z = fmaf(g3, v3.z, b3); o.w = fmaf(g3, v3.w, b3);
    out[base + 768] = o;
    o.x = fmaf(g4, v4.x, b4); o.y = fmaf(g4, v4.y, b4);
    o.z = fmaf(g4, v4.z, b4); o.w = fmaf(g4, v4.w, b4);
    out[base + 1024] = o;
    o.x = fmaf(g5, v5.x, b5); o.y = fmaf(g5, v5.y, b5);
    o.z = fmaf(g5, v5.z, b5); o.w = fmaf(g5, v5.w, b5);
    out[base + 1280] = o;
    o.x = fmaf(g6, v6.x, b6); o.y = fmaf(g6, v6.y, b6);
    o.z = fmaf(g6, v6.z, b6); o.w = fmaf(g6, v6.w, b6);
    out[base + 1536] = o;
    o.x = fmaf(g7, v7.x, b7); o.y = fmaf(g7, v7.y, b7);
    o.z = fmaf(g7, v7.z, b7); o.w = fmaf(g7, v7.w, b7);
    out[base + 1792] = o;
}

// ---------------------------------------------------------------------------
extern "C" void kernel_launch(void* const* d_in, const int* in_sizes, int n_in,
                              void* d_out, int out_size) {
    const float* x    = (const float*)d_in[0];   // [T,B,C,H,W]
    const float* cond = (const float*)d_in[1];   // [T,B,Cc]
    const float* Wm   = (const float*)d_in[2];   // [2C,Cc]
    const float* bias = (const float*)d_in[3];   // [2C]
    float* out = (float*)d_out;

    fused_kernel<<<TT * BB * CC / 8, 256>>>(
        (const float4*)x, cond, Wm, bias, (float4*)out);
}

// round 13
// speedup vs baseline: 1.1698x; 1.0160x over previous
#include <cuda_runtime.h>
#include <cuda_bf16.h>
#include <cstdint>

#define TT 16          // time steps
#define BB 16          // batch
#define CC 256         // channels C (and Cc)
#define DD 512         // 2*C
#define HW 1024        // H*W

// ---------------------------------------------------------------------------
// Single fused kernel, one launch. Grid = 8192 blocks x 256 threads; block
// owns 8 consecutive channels of one (t,b) slice (the measured-77us tiling).
// Identical to the 85.4us R10 winner except Phase C uses streaming
// loads/stores (__ldcs/__stcs): x is read-once, out is write-once ->
// evict-first keeps L2 clean of dead lines.
//
// Phase A: block-local LIF scan; thread cc loads cond[(t',b,cc)] for all 16
//          t' (independent -> MLP=16, L2-resident after first wave), runs the
//          recurrence in registers, keeps the spike at THIS block's t.
// Phase B: the 16 params this block needs = 16 dot products of length 256.
//          16 threads per output, conflict-free smem + coalesced W,
//          4-stage shfl reduce.
// Phase C: MLP=8 FiLM body, streaming hints.
// ---------------------------------------------------------------------------
__global__ void __launch_bounds__(256) fused_kernel(
    const float4* __restrict__ x,
    const float*  __restrict__ cond,
    const float*  __restrict__ Wm,
    const float*  __restrict__ bias,
    float4*       __restrict__ out) {
    __shared__ float s_sp[CC];      // spikes at this block's t
    __shared__ float s_par[16];     // 8 gamma | 8 beta

    int tid  = threadIdx.x;
    unsigned row0 = blockIdx.x * 8;         // first channel-row
    unsigned tb   = row0 >> 8;              // t*BB + b
    unsigned c0   = row0 & (CC - 1);
    int t = (int)(tb >> 4);                 // this block's time step
    int b = (int)(tb & 15);

    // --- Phase A: LIF scan for (b, cc=tid); keep spike at step t ---
    {
        int cc = tid;
        float xv[TT];
#pragma unroll
        for (int tp = 0; tp < TT; ++tp)     // independent loads, MLP=16
            xv[tp] = cond[(tp * BB + b) * CC + cc];
        float v = 0.0f, s_t = 0.0f;
#pragma unroll
        for (int tp = 0; tp < TT; ++tp) {
            v = v + (xv[tp] - v) * 0.5f;             // charge (TAU=2)
            float s = (v >= 1.0f) ? 1.0f : 0.0f;     // fire
            if (tp == t) s_t = s;                    // predicated select
            v = (1.0f - s) * v;                      // hard reset
        }
        s_sp[cc] = s_t;
    }
    __syncthreads();

    // --- Phase B: 16 dot products (8 gamma rows, 8 beta rows) ---
    {
        int o  = tid >> 4;                  // output 0..15
        int ch = tid & 15;                  // k-chunk lane 0..15
        int d  = (o < 8) ? (int)(c0 + o) : (int)(CC + c0 + (o - 8));
        const float* __restrict__ wr = Wm + (size_t)d * CC;

        float a = 0.0f;
#pragma unroll
        for (int i = 0; i < 16; ++i) {
            int k = i * 16 + ch;            // conflict-free smem, coalesced W
            a = fmaf(s_sp[k], wr[k], a);
        }
#pragma unroll
        for (int m = 8; m >= 1; m >>= 1)    // reduce within 16-lane group
            a += __shfl_xor_sync(0xFFFFFFFFu, a, m);
        if (ch == 0) s_par[o] = a + bias[d];
    }
    __syncthreads();

    // --- Phase C: FiLM body, streaming loads/stores ---
    size_t base = (size_t)row0 * 256 + tid;

    float4 v0 = __ldcs(&x[base]);
    float4 v1 = __ldcs(&x[base + 256]);
    float4 v2 = __ldcs(&x[base + 512]);
    float4 v3 = __ldcs(&x[base + 768]);
    float4 v4 = __ldcs(&x[base + 1024]);
    float4 v5 = __ldcs(&x[base + 1280]);
    float4 v6 = __ldcs(&x[base + 1536]);
    float4 v7 = __ldcs(&x[base + 1792]);

    float g0 = 1.0f + s_par[0], g1 = 1.0f + s_par[1];
    float g2 = 1.0f + s_par[2], g3 = 1.0f + s_par[3];
    float g4 = 1.0f + s_par[4], g5 = 1.0f + s_par[5];
    float g6 = 1.0f + s_par[6], g7 = 1.0f + s_par[7];
    float b0 = s_par[8],  b1 = s_par[9],  b2 = s_par[10], b3 = s_par[11];
    float b4 = s_par[12], b5 = s_par[13], b6 = s_par[14], b7 = s_par[15];

    float4 o;
    o.x = fmaf(g0, v0.x, b0); o.y = fmaf(g0, v0.y, b0);
    o.z = fmaf(g0, v0.z, b0); o.w = fmaf(g0, v0.w, b0);
    __stcs(&out[base], o);
    o.x = fmaf(g1, v1.x, b1); o.y = fmaf(g1, v1.y, b1);
    o.z = fmaf(g1, v1.z, b1); o.w = fmaf(g1, v1.w, b1);
    __stcs(&out[base + 256], o);
    o.x = fmaf(g2, v2.x, b2); o.y = fmaf(g2, v2.y, b2);
    o.z = fmaf(g2, v2.z, b2); o.w = fmaf(g2, v2.w, b2);
    __stcs(&out[base + 512], o);
    o.x = fmaf(g3, v3.x, b3); o.y = fmaf(g3, v3.y, b3);
    o.z = fmaf(g3, v3.z, b3); o.w = fmaf(g3, v3.w, b3);
    __stcs(&out[base + 768], o);
    o.x = fmaf(g4, v4.x, b4); o.y = fmaf(g4, v4.y, b4);
    o.z = fmaf(g4, v4.z, b4); o.w = fmaf(g4, v4.w, b4);
    __stcs(&out[base + 1024], o);
    o.x = fmaf(g5, v5.x, b5); o.y = fmaf(g5, v5.y, b5);
    o.z = fmaf(g5, v5.z, b5); o.w = fmaf(g5, v5.w, b5);
    __stcs(&out[base + 1280], o);
    o.x = fmaf(g6, v6.x, b6); o.y = fmaf(g6, v6.y, b6);
    o.z = fmaf(g6, v6.z, b6); o.w = fmaf(g6, v6.w, b6);
    __stcs(&out[base + 1536], o);
    o.x = fmaf(g7, v7.x, b7); o.y = fmaf(g7, v7.y, b7);
    o.z = fmaf(g7, v7.z, b7); o.w = fmaf(g7, v7.w, b7);
    __stcs(&out[base + 1792], o);
}

// ---------------------------------------------------------------------------
extern "C" void kernel_launch(void* const* d_in, const int* in_sizes, int n_in,
                              void* d_out, int out_size) {
    const float* x    = (const float*)d_in[0];   // [T,B,C,H,W]
    const float* cond = (const float*)d_in[1];   // [T,B,Cc]
    const float* Wm   = (const float*)d_in[2];   // [2C,Cc]
    const float* bias = (const float*)d_in[3];   // [2C]
    float* out = (float*)d_out;

    fused_kernel<<<TT * BB * CC / 8, 256>>>(
        (const float4*)x, cond, Wm, bias, (float4*)out);
}